// round 17
// baseline (speedup 1.0000x reference)
#include <cuda_runtime.h>
#include <cuda_bf16.h>
#include <cstdint>

// ============================================================================
// GraphSAGE 2-layer, mean aggregation. CSR gather-reduce + tf32 mma.sync GEMMs.
// bf16 gather tables (yl, p), fp32 accumulate. 4-warp 64x64-tile GEMM.
//   yl(bf16), yr(f32) = x@Wl0, x@Wr0   (one launch, blockIdx.y selects)
//   h   = relu(agg(yl)/deg + yr + bl0)            (fused CSR gather)
//   p(bf16), q(f32)   = h@[Wl1|Wr1]               (split epilogue)
//   out = agg(p)/deg + q + bl1                    (fused CSR gather)
// ============================================================================

#define NMAX 100000
#define EMAX 1600000
#define SCAN_B 1024
#define NBLK ((NMAX + SCAN_B - 1) / SCAN_B)

__device__ __nv_bfloat16 g_YLB[NMAX * 128];  // bf16 gather table, layer 0
__device__ float         g_YR [NMAX * 128];
__device__ float         g_H  [NMAX * 128];
__device__ __nv_bfloat16 g_PB [NMAX * 64];   // bf16 gather table, layer 1
__device__ float         g_QB [NMAX * 64];
__device__ float         g_WT0[256 * 128];   // [n][k] tf32-rounded
__device__ float         g_WT1[128 * 128];
__device__ int2          g_EDGE[EMAX];
__device__ int           g_SRC [EMAX];
__device__ int           g_DEG [NMAX];
__device__ int           g_OFF [NMAX];
__device__ int           g_CUR [NMAX];
__device__ int           g_BSUM[NBLK];
__device__ int           g_FLAG;

__device__ __forceinline__ uint32_t f2tf32(float v) {
    uint32_t t; asm("cvt.rna.tf32.f32 %0, %1;" : "=r"(t) : "f"(v)); return t;
}
__device__ __forceinline__ void mma_tf32(float* c, const uint32_t* a,
                                         uint32_t b0, uint32_t b1) {
    asm volatile(
        "mma.sync.aligned.m16n8k8.row.col.f32.tf32.tf32.f32 "
        "{%0,%1,%2,%3}, {%4,%5,%6,%7}, {%8,%9}, {%0,%1,%2,%3};"
        : "+f"(c[0]), "+f"(c[1]), "+f"(c[2]), "+f"(c[3])
        : "r"(a[0]), "r"(a[1]), "r"(a[2]), "r"(a[3]), "r"(b0), "r"(b1));
}

// ============================================================================
// init: zero DEG + parallel edge-dtype detection (warp ballot, block 0)
// ============================================================================
__global__ void init_kernel(int* __restrict__ deg, int n,
                            const int* __restrict__ raw, int nwords,
                            int* __restrict__ flag)
{
    int i = blockIdx.x * blockDim.x + threadIdx.x;
    if (i < n) deg[i] = 0;
    if (blockIdx.x == 0 && threadIdx.x < 32) {
        // int64 storage => all odd 32-bit words of first 256 are zero
        int ok = 1;
#pragma unroll
        for (int k = 0; k < 4; k++) {
            int idx = 1 + 2 * (threadIdx.x + 32 * k);
            if (idx < nwords && idx < 256 && raw[idx] != 0) ok = 0;
        }
        unsigned all = __ballot_sync(0xFFFFFFFFu, ok);
        if (threadIdx.x == 0) *flag = (all == 0xFFFFFFFFu) ? 1 : 0;
    }
}

__global__ void decode_edges(const void* __restrict__ eiraw, int E, int N,
                             const int* __restrict__ flag,
                             int2* __restrict__ edge, int* __restrict__ deg)
{
    int e = blockIdx.x * blockDim.x + threadIdx.x;
    if (e >= E) return;
    int s, d;
    if (*flag) {
        const long long* p = (const long long*)eiraw;
        s = (int)p[e]; d = (int)p[(size_t)E + e];
    } else {
        const int* p = (const int*)eiraw;
        s = p[e]; d = p[(size_t)E + e];
    }
    s = min(max(s, 0), N - 1);
    d = min(max(d, 0), N - 1);
    edge[e] = make_int2(s, d);
    atomicAdd(&deg[d], 1);
}

__global__ __launch_bounds__(SCAN_B) void scan1(
    const int* __restrict__ deg, int N, int* __restrict__ excl, int* __restrict__ bsum)
{
    __shared__ int sh[SCAN_B];
    int gid = blockIdx.x * SCAN_B + threadIdx.x;
    int v = (gid < N) ? deg[gid] : 0;
    sh[threadIdx.x] = v;
    __syncthreads();
#pragma unroll
    for (int off = 1; off < SCAN_B; off <<= 1) {
        int t = (threadIdx.x >= off) ? sh[threadIdx.x - off] : 0;
        __syncthreads();
        sh[threadIdx.x] += t;
        __syncthreads();
    }
    if (gid < N) excl[gid] = sh[threadIdx.x] - v;
    if (threadIdx.x == SCAN_B - 1) bsum[blockIdx.x] = sh[SCAN_B - 1];
}
__global__ void scan2(int* __restrict__ bsum, int nb) {
    if (blockIdx.x == 0 && threadIdx.x == 0) {
        int acc = 0;
        for (int i = 0; i < nb; i++) { int v = bsum[i]; bsum[i] = acc; acc += v; }
    }
}
__global__ void scan3(int* __restrict__ off, const int* __restrict__ bsum,
                      int N, int* __restrict__ cur)
{
    int gid = blockIdx.x * blockDim.x + threadIdx.x;
    if (gid < N) {
        int o = off[gid] + bsum[gid >> 10];
        off[gid] = o;
        cur[gid] = o;
    }
}
__global__ void fill_csr(const int2* __restrict__ edge, int E,
                         int* __restrict__ cur, int* __restrict__ srcarr)
{
    int e = blockIdx.x * blockDim.x + threadIdx.x;
    if (e >= E) return;
    int2 sd = edge[e];
    int slot = atomicAdd(&cur[sd.y], 1);
    srcarr[slot] = sd.x;
}

// ============================================================================
// Weight prep (fused): WT0 [256x128] then WT1 [128x128], transpose + tf32.
// ============================================================================
__global__ void prep_wt(const float* __restrict__ Wl0, const float* __restrict__ Wr0,
                        const float* __restrict__ Wl1, const float* __restrict__ Wr1,
                        float* __restrict__ WT0, float* __restrict__ WT1)
{
    int i = blockIdx.x * blockDim.x + threadIdx.x;
    if (i < 256 * 128) {
        int n = i >> 7, k = i & 127;
        float v = (n < 128) ? Wl0[k * 128 + n] : Wr0[k * 128 + (n - 128)];
        WT0[i] = __uint_as_float(f2tf32(v));
    } else if (i < 256 * 128 + 128 * 128) {
        int j = i - 256 * 128;
        int n = j >> 7, k = j & 127;
        float v = (n < 64) ? Wl1[k * 64 + n] : Wr1[k * 64 + (n - 64)];
        WT1[j] = __uint_as_float(f2tf32(v));
    }
}

// ============================================================================
// tf32 mma.sync GEMM: C[128,128] = A_tile[128,128] @ B^T per CTA.
// 4 warps (2x2), warp tile 64x64 via 4x8 m16n8k8 fragments. BK=32, pad 36.
// 32 LDS : 32 HMMA per warp per kk-step (balanced).
// Output modes: 0 = fp32 full; 1 = bf16 full; 2 = split (bf16 low / f32 high).
// blockIdx.y selects the 128-row BT slab + output set.
// ============================================================================
#define PADK 36
__global__ __launch_bounds__(128) void gemm_mma(
    const float* __restrict__ A, const float* __restrict__ BT,
    void* outA0, void* outB0, int mode0,
    void* outA1, void* outB1, int mode1, int nrows)
{
    __shared__ float As[128][PADK];
    __shared__ float Bs[128][PADK];

    const float* B   = BT + (size_t)blockIdx.y * 128 * 128;
    void* outA = blockIdx.y ? outA1 : outA0;
    void* outB = blockIdx.y ? outB1 : outB0;
    const int mode = blockIdx.y ? mode1 : mode0;

    const int tid  = threadIdx.x;
    const int wid  = tid >> 5, lane = tid & 31;
    const int g    = lane >> 2, tig = lane & 3;
    const int wm   = wid >> 1,  wn  = wid & 1;     // 2 x 2 warp grid
    const int row0 = blockIdx.x * 128;

    float acc[4][8][4];
#pragma unroll
    for (int mt = 0; mt < 4; mt++)
#pragma unroll
        for (int nt = 0; nt < 8; nt++)
#pragma unroll
            for (int q = 0; q < 4; q++) acc[mt][nt][q] = 0.f;

    for (int k0 = 0; k0 < 128; k0 += 32) {
        // A chunk 128x32: 1024 float4 over 128 threads (8 each), cvt -> tf32
#pragma unroll
        for (int i = 0; i < 8; i++) {
            int f = tid + i * 128;
            int r = f >> 3, c = (f & 7) << 2;
            float4 v = make_float4(0.f, 0.f, 0.f, 0.f);
            if (row0 + r < nrows)
                v = *(const float4*)&A[(size_t)(row0 + r) * 128 + k0 + c];
            As[r][c + 0] = __uint_as_float(f2tf32(v.x));
            As[r][c + 1] = __uint_as_float(f2tf32(v.y));
            As[r][c + 2] = __uint_as_float(f2tf32(v.z));
            As[r][c + 3] = __uint_as_float(f2tf32(v.w));
        }
        // B chunk 128x32 (already tf32-rounded)
#pragma unroll
        for (int i = 0; i < 8; i++) {
            int f = tid + i * 128;
            int r = f >> 3, c = (f & 7) << 2;
            float4 v = *(const float4*)&B[(size_t)r * 128 + k0 + c];
            *(float4*)&Bs[r][c] = v;
        }
        __syncthreads();

#pragma unroll
        for (int kk = 0; kk < 32; kk += 8) {
            uint32_t af[4][4];
#pragma unroll
            for (int mt = 0; mt < 4; mt++) {
                int r = wm * 64 + mt * 16 + g;
                af[mt][0] = __float_as_uint(As[r    ][kk + tig    ]);
                af[mt][1] = __float_as_uint(As[r + 8][kk + tig    ]);
                af[mt][2] = __float_as_uint(As[r    ][kk + tig + 4]);
                af[mt][3] = __float_as_uint(As[r + 8][kk + tig + 4]);
            }
#pragma unroll
            for (int nt = 0; nt < 8; nt++) {
                int n = wn * 64 + nt * 8 + g;
                uint32_t b0 = __float_as_uint(Bs[n][kk + tig    ]);
                uint32_t b1 = __float_as_uint(Bs[n][kk + tig + 4]);
#pragma unroll
                for (int mt = 0; mt < 4; mt++)
                    mma_tf32(acc[mt][nt], af[mt], b0, b1);
            }
        }
        __syncthreads();
    }

    // epilogue: fragment (mt, half): row wm*64+mt*16+g+half*8; col wn*64+nt*8+2tig
#pragma unroll
    for (int mt = 0; mt < 4; mt++) {
#pragma unroll
        for (int half = 0; half < 2; half++) {
            int r = row0 + wm * 64 + mt * 16 + g + half * 8;
            if (r >= nrows) continue;
#pragma unroll
            for (int nt = 0; nt < 8; nt++) {
                int col = wn * 64 + nt * 8 + 2 * tig;
                float v0 = acc[mt][nt][half * 2 + 0];
                float v1 = acc[mt][nt][half * 2 + 1];
                if (mode == 0) {
                    *(float2*)&((float*)outA)[(size_t)r * 128 + col] =
                        make_float2(v0, v1);
                } else if (mode == 1) {
                    *(__nv_bfloat162*)&((__nv_bfloat16*)outA)[(size_t)r * 128 + col] =
                        __floats2bfloat162_rn(v0, v1);
                } else {
                    if (wn == 0)
                        *(__nv_bfloat162*)&((__nv_bfloat16*)outA)[(size_t)r * 64 + col] =
                            __floats2bfloat162_rn(v0, v1);
                    else
                        *(float2*)&((float*)outB)[(size_t)r * 64 + (col - 64)] =
                            make_float2(v0, v1);
                }
            }
        }
    }
}

// ============================================================================
// Fused CSR gather-reduce + combine. bf16 gather tables, fp32 accumulate.
// ============================================================================
__global__ __launch_bounds__(256) void agg_combine_relu(
    const int* __restrict__ off, const int* __restrict__ deg,
    const int* __restrict__ srcarr,
    const __nv_bfloat16* __restrict__ YLB, const float* __restrict__ YR,
    const float* __restrict__ bias,
    float* __restrict__ H, int n)
{
    int warp = (blockIdx.x * 256 + threadIdx.x) >> 5;
    int lane = threadIdx.x & 31;
    if (warp >= n) return;
    int start = off[warp], len = deg[warp];
    int c = lane << 2;

    float4 acc = make_float4(0.f, 0.f, 0.f, 0.f);
    int j = 0;
    for (; j + 8 <= len; j += 8) {
        int s[8];
#pragma unroll
        for (int u = 0; u < 8; u++) s[u] = __ldg(&srcarr[start + j + u]);
        uint2 raw[8];
#pragma unroll
        for (int u = 0; u < 8; u++)
            raw[u] = __ldg((const uint2*)&YLB[(size_t)s[u] * 128 + c]);
#pragma unroll
        for (int u = 0; u < 8; u++) {
            float2 a = __bfloat1622float2(*(__nv_bfloat162*)&raw[u].x);
            float2 b = __bfloat1622float2(*(__nv_bfloat162*)&raw[u].y);
            acc.x += a.x; acc.y += a.y; acc.z += b.x; acc.w += b.y;
        }
    }
    for (; j < len; j++) {
        int s = __ldg(&srcarr[start + j]);
        uint2 raw = __ldg((const uint2*)&YLB[(size_t)s * 128 + c]);
        float2 a = __bfloat1622float2(*(__nv_bfloat162*)&raw.x);
        float2 b = __bfloat1622float2(*(__nv_bfloat162*)&raw.y);
        acc.x += a.x; acc.y += a.y; acc.z += b.x; acc.w += b.y;
    }

    float inv = 1.0f / fmaxf((float)len, 1.0f);
    float4 y = *(const float4*)&YR[(size_t)warp * 128 + c];
    float4 b = *(const float4*)&bias[c];
    float4 o;
    o.x = fmaxf(fmaf(acc.x, inv, y.x + b.x), 0.f);
    o.y = fmaxf(fmaf(acc.y, inv, y.y + b.y), 0.f);
    o.z = fmaxf(fmaf(acc.z, inv, y.z + b.z), 0.f);
    o.w = fmaxf(fmaf(acc.w, inv, y.w + b.w), 0.f);
    *(float4*)&H[(size_t)warp * 128 + c] = o;
}

__global__ __launch_bounds__(256) void agg_combine_out(
    const int* __restrict__ off, const int* __restrict__ deg,
    const int* __restrict__ srcarr,
    const __nv_bfloat16* __restrict__ PB, const float* __restrict__ QB,
    const float* __restrict__ bias,
    float* __restrict__ out, int n)
{
    int warp = (blockIdx.x * 256 + threadIdx.x) >> 5;
    int lane = threadIdx.x & 31;
    if (warp >= n) return;
    int start = off[warp], len = deg[warp];
    int c = lane << 1;

    float2 acc = make_float2(0.f, 0.f);
    int j = 0;
    for (; j + 8 <= len; j += 8) {
        int s[8];
#pragma unroll
        for (int u = 0; u < 8; u++) s[u] = __ldg(&srcarr[start + j + u]);
        uint32_t raw[8];
#pragma unroll
        for (int u = 0; u < 8; u++)
            raw[u] = __ldg((const uint32_t*)&PB[(size_t)s[u] * 64 + c]);
#pragma unroll
        for (int u = 0; u < 8; u++) {
            float2 v = __bfloat1622float2(*(__nv_bfloat162*)&raw[u]);
            acc.x += v.x; acc.y += v.y;
        }
    }
    for (; j < len; j++) {
        int s = __ldg(&srcarr[start + j]);
        uint32_t raw = __ldg((const uint32_t*)&PB[(size_t)s * 64 + c]);
        float2 v = __bfloat1622float2(*(__nv_bfloat162*)&raw);
        acc.x += v.x; acc.y += v.y;
    }

    float inv = 1.0f / fmaxf((float)len, 1.0f);
    float2 q = *(const float2*)&QB[(size_t)warp * 64 + c];
    float2 b = *(const float2*)&bias[c];
    float2 o;
    o.x = fmaf(acc.x, inv, q.x + b.x);
    o.y = fmaf(acc.y, inv, q.y + b.y);
    *(float2*)&out[(size_t)warp * 64 + c] = o;
}

// ============================================================================
// kernel_launch — graph-capturable, allocation-free, deterministic per call.
// ============================================================================
extern "C" void kernel_launch(void* const* d_in, const int* in_sizes, int n_in,
                              void* d_out, int out_size)
{
    const float* x   = (const float*)d_in[0];
    const void*  ei  = d_in[1];
    const float* Wl0 = (const float*)d_in[2];
    const float* bl0 = (const float*)d_in[3];
    const float* Wr0 = (const float*)d_in[4];
    const float* Wl1 = (const float*)d_in[5];
    const float* bl1 = (const float*)d_in[6];
    const float* Wr1 = (const float*)d_in[7];
    float*       out = (float*)d_out;

    const int N = in_sizes[0] / 128;   // 100000
    const int E = in_sizes[1] / 2;     // 1600000

    __nv_bfloat16 *YLB, *PB;
    float *YR, *H, *QB, *WT0, *WT1;
    int2* EDGE; int *SRC, *DEG, *OFF, *CUR, *BSUM, *FLAG;
    cudaGetSymbolAddress((void**)&YLB,  g_YLB);
    cudaGetSymbolAddress((void**)&YR,   g_YR);
    cudaGetSymbolAddress((void**)&H,    g_H);
    cudaGetSymbolAddress((void**)&PB,   g_PB);
    cudaGetSymbolAddress((void**)&QB,   g_QB);
    cudaGetSymbolAddress((void**)&WT0,  g_WT0);
    cudaGetSymbolAddress((void**)&WT1,  g_WT1);
    cudaGetSymbolAddress((void**)&EDGE, g_EDGE);
    cudaGetSymbolAddress((void**)&SRC,  g_SRC);
    cudaGetSymbolAddress((void**)&DEG,  g_DEG);
    cudaGetSymbolAddress((void**)&OFF,  g_OFF);
    cudaGetSymbolAddress((void**)&CUR,  g_CUR);
    cudaGetSymbolAddress((void**)&BSUM, g_BSUM);
    cudaGetSymbolAddress((void**)&FLAG, g_FLAG);

    const int TPB = 256;
    const int nScanBlk = (N + SCAN_B - 1) / SCAN_B;

    // 1: zero DEG + edge dtype detect (fused)
    init_kernel<<<(N + TPB - 1) / TPB, TPB>>>(DEG, N, (const int*)ei,
                                              in_sizes[1], FLAG);
    // 2: decode + degree histogram
    decode_edges<<<(E + TPB - 1) / TPB, TPB>>>(ei, E, N, FLAG, EDGE, DEG);
    // 3: weight prep (fused)
    prep_wt<<<(256 * 128 + 128 * 128 + TPB - 1) / TPB, TPB>>>(
        Wl0, Wr0, Wl1, Wr1, WT0, WT1);
    // 4: layer 0 dual GEMM: y=0 -> yl (bf16 full), y=1 -> yr (f32 full)
    {
        dim3 grid((N + 127) / 128, 2);
        gemm_mma<<<grid, 128>>>(x, WT0,
                                (void*)YLB, nullptr, 1,
                                (void*)YR,  nullptr, 0, N);
    }
    // 5-8: CSR build
    scan1<<<nScanBlk, SCAN_B>>>(DEG, N, OFF, BSUM);
    scan2<<<1, 32>>>(BSUM, nScanBlk);
    scan3<<<(N + TPB - 1) / TPB, TPB>>>(OFF, BSUM, N, CUR);
    fill_csr<<<(E + TPB - 1) / TPB, TPB>>>(EDGE, E, CUR, SRC);
    // 9: layer 0 aggregation + combine + relu
    agg_combine_relu<<<(N * 32 + TPB - 1) / TPB, TPB>>>(
        OFF, DEG, SRC, YLB, YR, bl0, H, N);
    // 10: layer 1 GEMM: split epilogue -> p (bf16), q (f32)
    {
        dim3 grid((N + 127) / 128, 1);
        gemm_mma<<<grid, 128>>>(H, WT1,
                                (void*)PB, (void*)QB, 2,
                                nullptr, nullptr, 0, N);
    }
    // 11: layer 1 aggregation + combine -> out
    agg_combine_out<<<(N * 32 + TPB - 1) / TPB, TPB>>>(
        OFF, DEG, SRC, PB, QB, bl1, out, N);
}